// round 16
// baseline (speedup 1.0000x reference)
#include <cuda_runtime.h>
#include <cuda_bf16.h>
#include <cstdint>

// TransportKernel via warp-level mma.sync (HMMA bf16) — R12.
// R9 ncu: issue=64%, tensor=33%, alu=31% -> issue-bound; cut non-HMMA slots.
//   - MMA2 (P@V) now plain bf16: 2 HMMA (was 6), no Pl/Vl corrections.
//     Analytic error ~1e-5 relative (random-sign 2e-3 P-error, sqrt-suppressed
//     in a diag-dominated positive quadratic form).
//   - dropped FMNMX clamp (diag overridden; off-diag arg>0 only via rounding).
//   - s_vtl deleted: smem fill per tile halves; smem 22->17 KB.
// MMA1 keeps full hi/lo (6 HMMA) — the d^2 path is precision-critical.
//
//   pass1: A = Kfit @ Lam   (gamma = -log2(e)/2)
//   pass2: W = Kmmd @ diff  (gamma = -log2(e)/8), diff = A - Y
//   loss = sum(diff .* W) + 0.01 * sum(Lam .* A)

#define N 8192
#define D 16
#define JS 8
#define JT 128
#define TILES_PER_CTA (N / JS / JT)   // 8
#define CHUNKS_PER_TILE (JT / 16)     // 8

#define LOG2E 1.4426950408889634f
#define GAMMA1 (-0.5f * LOG2E)
#define GAMMA2 (-0.125f * LOG2E)

#define XROW 48                  // padded Xj smem row stride (bytes)
#define VROW 136                 // Vt smem row stride (bf16 elems)

__device__ float g_sq[N];
__device__ float g_A[N * D];
__device__ float g_diff[N * D];
__device__ float g_W[N * D];

// ---------------------------------------------------------------------------
__device__ __forceinline__ uint32_t bf16x2(float lo, float hi) {
    uint32_t r;
    asm("cvt.rn.bf16x2.f32 %0, %1, %2;" : "=r"(r) : "f"(hi), "f"(lo));
    return r;
}
__device__ __forceinline__ float ex2a(float x) {
    float y;
    asm("ex2.approx.f32 %0, %1;" : "=f"(y) : "f"(x));
    return y;
}
__device__ __forceinline__ float lo_of(uint32_t p) { return __uint_as_float(p << 16); }
__device__ __forceinline__ float hi_of(uint32_t p) { return __uint_as_float(p & 0xffff0000u); }
__device__ __forceinline__ void hilo2(float x, float y, uint32_t& h, uint32_t& l) {
    h = bf16x2(x, y);
    l = bf16x2(x - lo_of(h), y - hi_of(h));
}
__device__ __forceinline__ void mma16816(float* d, const uint32_t* a,
                                         uint32_t b0, uint32_t b1) {
    asm volatile("mma.sync.aligned.m16n8k16.row.col.f32.bf16.bf16.f32 "
                 "{%0,%1,%2,%3}, {%4,%5,%6,%7}, {%8,%9}, {%0,%1,%2,%3};"
                 : "+f"(d[0]), "+f"(d[1]), "+f"(d[2]), "+f"(d[3])
                 : "r"(a[0]), "r"(a[1]), "r"(a[2]), "r"(a[3]), "r"(b0), "r"(b1));
}

// ---------------------------------------------------------------------------
__global__ void __launch_bounds__(256) prep_kernel(const float* __restrict__ X,
                                                   float* __restrict__ out) {
    int i = blockIdx.x * 256 + threadIdx.x;
    if (i == 0) out[0] = 0.0f;
    const float4* xp = (const float4*)(X + (size_t)i * D);
    float s = 0.0f;
    float4 z = make_float4(0.f, 0.f, 0.f, 0.f);
    float4* ap = (float4*)(g_A + (size_t)i * D);
#pragma unroll
    for (int k = 0; k < 4; k++) {
        float4 v = xp[k];
        s += v.x * v.x + v.y * v.y + v.z * v.z + v.w * v.w;
        ap[k] = z;
    }
    g_sq[i] = s;
}

// ---------------------------------------------------------------------------
// rbf_mv: Wout += K_gamma(X) @ V ; mode 0: V=Lam -> g_A ; 1: V=g_diff -> g_W
// 256 threads = 8 warps; warp w owns 16 i-rows
// ---------------------------------------------------------------------------
__global__ void __launch_bounds__(256) rbf_mv_kernel(const float* __restrict__ X,
                                                     const float* __restrict__ Lam,
                                                     float gamma, int mode) {
    __shared__ __align__(16) unsigned char s_xh[JT * XROW];      // Xj hi bf16 [j][d]
    __shared__ __align__(16) unsigned char s_xl[JT * XROW];      // Xj lo
    __shared__ __nv_bfloat16 s_vth[D * VROW];                    // V^T hi [d][j]
    __shared__ float s_cs[JT];                                   // gamma*sq_j

    const float* V = mode ? g_diff : Lam;
    float* Wout    = mode ? g_W    : g_A;

    const int tid  = threadIdx.x;
    const int lane = tid & 31;
    const int w    = tid >> 5;
    const int g    = lane >> 2;
    const int tg   = lane & 3;

    const int i0   = blockIdx.x * 128 + w * 16;
    const int row0 = i0 + g;
    const int row1 = i0 + g + 8;

    // --- A fragments for Xi (hi & lo), fixed for whole kernel ---
    uint32_t Ah[4], Al[4];
    {
        const float* r0 = X + (size_t)row0 * D;
        const float* r1 = X + (size_t)row1 * D;
        float2 p0 = *(const float2*)(r0 + 2 * tg);
        float2 p1 = *(const float2*)(r1 + 2 * tg);
        float2 p2 = *(const float2*)(r0 + 2 * tg + 8);
        float2 p3 = *(const float2*)(r1 + 2 * tg + 8);
        hilo2(p0.x, p0.y, Ah[0], Al[0]);
        hilo2(p1.x, p1.y, Ah[1], Al[1]);
        hilo2(p2.x, p2.y, Ah[2], Al[2]);
        hilo2(p3.x, p3.y, Ah[3], Al[3]);
    }
    const float base0 = gamma * g_sq[row0];
    const float base1 = gamma * g_sq[row1];

    float Wacc[8];
#pragma unroll
    for (int k = 0; k < 8; k++) Wacc[k] = 0.0f;

#pragma unroll 1
    for (int t = 0; t < TILES_PER_CTA; t++) {
        const int jt = blockIdx.y * (N / JS) + t * JT;
        __syncthreads();

        // ---- fill shared: Xj hi/lo [j][d], V^T hi [d][j], cs ----
        {
            const int r  = tid >> 1;
            const int dh = (tid & 1) * 8;
            const float4* xr = (const float4*)(X + (size_t)(jt + r) * D + dh);
            float4 a = xr[0], b = xr[1];
            uint32_t h0, l0, h1, l1, h2, l2, h3, l3;
            hilo2(a.x, a.y, h0, l0);
            hilo2(a.z, a.w, h1, l1);
            hilo2(b.x, b.y, h2, l2);
            hilo2(b.z, b.w, h3, l3);
            *(uint4*)(s_xh + r * XROW + dh * 2) = make_uint4(h0, h1, h2, h3);
            *(uint4*)(s_xl + r * XROW + dh * 2) = make_uint4(l0, l1, l2, l3);

            const float4* vr = (const float4*)(V + (size_t)(jt + r) * D + dh);
            float4 va = vr[0], vb = vr[1];
            float vv[8] = {va.x, va.y, va.z, va.w, vb.x, vb.y, vb.z, vb.w};
#pragma unroll
            for (int d = 0; d < 8; d++)
                s_vth[(dh + d) * VROW + r] = __float2bfloat16(vv[d]);
            if (tid < JT) s_cs[tid] = gamma * g_sq[jt + tid];
        }
        __syncthreads();

#pragma unroll 1
        for (int c = 0; c < CHUNKS_PER_TILE; c++) {
            const int jc    = c * 16;
            const int jglob = jt + jc;

            // ---- MMA1: S = Xi @ Xj^T (hi/lo split, 6 mma) ----
            float S[8];
#pragma unroll
            for (int k = 0; k < 8; k++) S[k] = 0.0f;
#pragma unroll
            for (int half = 0; half < 2; half++) {
                const int jr = jc + half * 8 + g;
                uint32_t bh0 = *(const uint32_t*)(s_xh + jr * XROW + 4 * tg);
                uint32_t bh1 = *(const uint32_t*)(s_xh + jr * XROW + 4 * tg + 16);
                uint32_t bl0 = *(const uint32_t*)(s_xl + jr * XROW + 4 * tg);
                uint32_t bl1 = *(const uint32_t*)(s_xl + jr * XROW + 4 * tg + 16);
                mma16816(S + half * 4, Ah, bh0, bh1);
                mma16816(S + half * 4, Al, bh0, bh1);
                mma16816(S + half * 4, Ah, bl0, bl1);
            }

            // ---- epilogue: p = exp2(gamma*d2), diag = 1 (no clamp needed) ----
            const float2 csA = *(const float2*)&s_cs[jc + 2 * tg];
            const float2 csB = *(const float2*)&s_cs[jc + 8 + 2 * tg];
            const float m2g = -2.0f * gamma;
            float p[8];
            p[0] = ex2a(fmaf(m2g, S[0], base0 + csA.x));
            p[1] = ex2a(fmaf(m2g, S[1], base0 + csA.y));
            p[2] = ex2a(fmaf(m2g, S[2], base1 + csA.x));
            p[3] = ex2a(fmaf(m2g, S[3], base1 + csA.y));
            p[4] = ex2a(fmaf(m2g, S[4], base0 + csB.x));
            p[5] = ex2a(fmaf(m2g, S[5], base0 + csB.y));
            p[6] = ex2a(fmaf(m2g, S[6], base1 + csB.x));
            p[7] = ex2a(fmaf(m2g, S[7], base1 + csB.y));
            if (i0 == jglob) {   // uniform per warp-chunk; exact diagonal k = 1
                const int jA = jglob + 2 * tg, jB = jglob + 8 + 2 * tg;
                if (row0 == jA)     p[0] = 1.0f;
                if (row0 == jA + 1) p[1] = 1.0f;
                if (row1 == jA)     p[2] = 1.0f;
                if (row1 == jA + 1) p[3] = 1.0f;
                if (row0 == jB)     p[4] = 1.0f;
                if (row0 == jB + 1) p[5] = 1.0f;
                if (row1 == jB)     p[6] = 1.0f;
                if (row1 == jB + 1) p[7] = 1.0f;
            }
            // D-fragment pair -> A-fragment repack, plain bf16
            uint32_t Ph[4];
            Ph[0] = bf16x2(p[0], p[1]);
            Ph[1] = bf16x2(p[2], p[3]);
            Ph[2] = bf16x2(p[4], p[5]);
            Ph[3] = bf16x2(p[6], p[7]);

            // ---- MMA2: Wacc += P @ V  (plain bf16, 2 mma) ----
#pragma unroll
            for (int nh = 0; nh < 2; nh++) {
                const int dr = nh * 8 + g;
                uint32_t vh0 = *(const uint32_t*)&s_vth[dr * VROW + jc + 2 * tg];
                uint32_t vh1 = *(const uint32_t*)&s_vth[dr * VROW + jc + 2 * tg + 8];
                mma16816(Wacc + nh * 4, Ph, vh0, vh1);
            }
        }
    }

    // ---- writeback ----
#pragma unroll
    for (int nh = 0; nh < 2; nh++) {
        const int col = nh * 8 + 2 * tg;
        atomicAdd(&Wout[(size_t)row0 * D + col],     Wacc[nh * 4 + 0]);
        atomicAdd(&Wout[(size_t)row0 * D + col + 1], Wacc[nh * 4 + 1]);
        atomicAdd(&Wout[(size_t)row1 * D + col],     Wacc[nh * 4 + 2]);
        atomicAdd(&Wout[(size_t)row1 * D + col + 1], Wacc[nh * 4 + 3]);
    }
}

// ---------------------------------------------------------------------------
__global__ void __launch_bounds__(256) mid_kernel(const float* __restrict__ Y) {
    int k = blockIdx.x * 256 + threadIdx.x;
    g_diff[k] = g_A[k] - Y[k];
    g_W[k] = 0.0f;
}

__global__ void __launch_bounds__(256) final_kernel(const float* __restrict__ Lam,
                                                    float* __restrict__ out) {
    __shared__ float s_red[8];
    float s = 0.0f;
    for (int k = blockIdx.x * 256 + threadIdx.x; k < N * D; k += gridDim.x * 256)
        s += g_diff[k] * g_W[k] + 0.01f * Lam[k] * g_A[k];
#pragma unroll
    for (int o = 16; o > 0; o >>= 1) s += __shfl_xor_sync(0xffffffffu, s, o);
    const int lane = threadIdx.x & 31, wd = threadIdx.x >> 5;
    if (lane == 0) s_red[wd] = s;
    __syncthreads();
    if (threadIdx.x == 0) {
        float t = 0.0f;
#pragma unroll
        for (int q = 0; q < 8; q++) t += s_red[q];
        atomicAdd(out, t);
    }
}

// ---------------------------------------------------------------------------
extern "C" void kernel_launch(void* const* d_in, const int* in_sizes, int n_in,
                              void* d_out, int out_size) {
    const float* X   = (const float*)d_in[0];
    const float* Y   = (const float*)d_in[1];
    const float* Lam = (const float*)d_in[2];
    float* out = (float*)d_out;

    prep_kernel<<<N / 256, 256>>>(X, out);

    dim3 grid(N / 128, JS);
    rbf_mv_kernel<<<grid, 256>>>(X, Lam, GAMMA1, 0);   // A = Kfit @ Lam
    mid_kernel<<<N * D / 256, 256>>>(Y);               // diff = A - Y, W = 0
    rbf_mv_kernel<<<grid, 256>>>(X, Lam, GAMMA2, 1);   // W = Kmmd @ diff
    final_kernel<<<128, 256>>>(Lam, out);
}

// round 17
// speedup vs baseline: 1.1249x; 1.1249x over previous
#include <cuda_runtime.h>
#include <cuda_bf16.h>
#include <cstdint>

// TransportKernel via warp-level mma.sync (HMMA bf16) — R16.
// R12 lesson: latency-bound, not issue-bound (removing instrs made it SLOWER).
// R16 = exact R9 datapath (6+6 HMMA, hi/lo everywhere, clamp, diag=1) plus a
// 2-chunk software pipeline: MMA1 of chunk c+1 issues before epilogue/MMA2 of
// chunk c, giving each warp an independent stream through the MUFU/CVT chain.
// __launch_bounds__(256,4) pins 4 CTAs/SM (one wave of 512 CTAs).
//
//   pass1: A = Kfit @ Lam   (gamma = -log2(e)/2)
//   pass2: W = Kmmd @ diff  (gamma = -log2(e)/8), diff = A - Y
//   loss = sum(diff .* W) + 0.01 * sum(Lam .* A)

#define N 8192
#define D 16
#define JS 8
#define JT 128
#define TILES_PER_CTA (N / JS / JT)   // 8
#define CHUNKS_PER_TILE (JT / 16)     // 8

#define LOG2E 1.4426950408889634f
#define GAMMA1 (-0.5f * LOG2E)
#define GAMMA2 (-0.125f * LOG2E)

#define XROW 48                  // padded Xj smem row stride (bytes)
#define VROW 136                 // Vt smem row stride (bf16 elems)

__device__ float g_sq[N];
__device__ float g_A[N * D];
__device__ float g_diff[N * D];
__device__ float g_W[N * D];

// ---------------------------------------------------------------------------
__device__ __forceinline__ uint32_t bf16x2(float lo, float hi) {
    uint32_t r;
    asm("cvt.rn.bf16x2.f32 %0, %1, %2;" : "=r"(r) : "f"(hi), "f"(lo));
    return r;
}
__device__ __forceinline__ float ex2a(float x) {
    float y;
    asm("ex2.approx.f32 %0, %1;" : "=f"(y) : "f"(x));
    return y;
}
__device__ __forceinline__ float lo_of(uint32_t p) { return __uint_as_float(p << 16); }
__device__ __forceinline__ float hi_of(uint32_t p) { return __uint_as_float(p & 0xffff0000u); }
__device__ __forceinline__ void hilo2(float x, float y, uint32_t& h, uint32_t& l) {
    h = bf16x2(x, y);
    l = bf16x2(x - lo_of(h), y - hi_of(h));
}
__device__ __forceinline__ void mma16816(float* d, const uint32_t* a,
                                         uint32_t b0, uint32_t b1) {
    asm volatile("mma.sync.aligned.m16n8k16.row.col.f32.bf16.bf16.f32 "
                 "{%0,%1,%2,%3}, {%4,%5,%6,%7}, {%8,%9}, {%0,%1,%2,%3};"
                 : "+f"(d[0]), "+f"(d[1]), "+f"(d[2]), "+f"(d[3])
                 : "r"(a[0]), "r"(a[1]), "r"(a[2]), "r"(a[3]), "r"(b0), "r"(b1));
}

// ---------------------------------------------------------------------------
__global__ void __launch_bounds__(256) prep_kernel(const float* __restrict__ X,
                                                   float* __restrict__ out) {
    int i = blockIdx.x * 256 + threadIdx.x;
    if (i == 0) out[0] = 0.0f;
    const float4* xp = (const float4*)(X + (size_t)i * D);
    float s = 0.0f;
    float4 z = make_float4(0.f, 0.f, 0.f, 0.f);
    float4* ap = (float4*)(g_A + (size_t)i * D);
#pragma unroll
    for (int k = 0; k < 4; k++) {
        float4 v = xp[k];
        s += v.x * v.x + v.y * v.y + v.z * v.z + v.w * v.w;
        ap[k] = z;
    }
    g_sq[i] = s;
}

// ---------------------------------------------------------------------------
// rbf_mv: Wout += K_gamma(X) @ V ; mode 0: V=Lam -> g_A ; 1: V=g_diff -> g_W
// 256 threads = 8 warps; warp w owns 16 i-rows. 2-chunk software pipeline.
// ---------------------------------------------------------------------------
__global__ void __launch_bounds__(256, 4) rbf_mv_kernel(const float* __restrict__ X,
                                                        const float* __restrict__ Lam,
                                                        float gamma, int mode) {
    __shared__ __align__(16) unsigned char s_xh[JT * XROW];      // Xj hi bf16 [j][d]
    __shared__ __align__(16) unsigned char s_xl[JT * XROW];      // Xj lo
    __shared__ __nv_bfloat16 s_vth[D * VROW];                    // V^T hi [d][j]
    __shared__ __nv_bfloat16 s_vtl[D * VROW];                    // V^T lo
    __shared__ float s_cs[JT];                                   // gamma*sq_j

    const float* V = mode ? g_diff : Lam;
    float* Wout    = mode ? g_W    : g_A;

    const int tid  = threadIdx.x;
    const int lane = tid & 31;
    const int w    = tid >> 5;
    const int g    = lane >> 2;
    const int tg   = lane & 3;

    const int i0   = blockIdx.x * 128 + w * 16;
    const int row0 = i0 + g;
    const int row1 = i0 + g + 8;

    // --- A fragments for Xi (hi & lo), fixed for whole kernel ---
    uint32_t Ah[4], Al[4];
    {
        const float* r0 = X + (size_t)row0 * D;
        const float* r1 = X + (size_t)row1 * D;
        float2 p0 = *(const float2*)(r0 + 2 * tg);
        float2 p1 = *(const float2*)(r1 + 2 * tg);
        float2 p2 = *(const float2*)(r0 + 2 * tg + 8);
        float2 p3 = *(const float2*)(r1 + 2 * tg + 8);
        hilo2(p0.x, p0.y, Ah[0], Al[0]);
        hilo2(p1.x, p1.y, Ah[1], Al[1]);
        hilo2(p2.x, p2.y, Ah[2], Al[2]);
        hilo2(p3.x, p3.y, Ah[3], Al[3]);
    }
    const float base0 = gamma * g_sq[row0];
    const float base1 = gamma * g_sq[row1];
    const float m2g = -2.0f * gamma;

    float Wacc[8];
#pragma unroll
    for (int k = 0; k < 8; k++) Wacc[k] = 0.0f;

    // ---- stage helpers ----
    auto mma1 = [&](int jc, float* S) {
#pragma unroll
        for (int k = 0; k < 8; k++) S[k] = 0.0f;
#pragma unroll
        for (int half = 0; half < 2; half++) {
            const int jr = jc + half * 8 + g;
            uint32_t bh0 = *(const uint32_t*)(s_xh + jr * XROW + 4 * tg);
            uint32_t bh1 = *(const uint32_t*)(s_xh + jr * XROW + 4 * tg + 16);
            uint32_t bl0 = *(const uint32_t*)(s_xl + jr * XROW + 4 * tg);
            uint32_t bl1 = *(const uint32_t*)(s_xl + jr * XROW + 4 * tg + 16);
            mma16816(S + half * 4, Ah, bh0, bh1);
            mma16816(S + half * 4, Al, bh0, bh1);
            mma16816(S + half * 4, Ah, bl0, bl1);
        }
    };
    auto epi_mma2 = [&](int jc, int jglob, const float* S) {
        const float2 csA = *(const float2*)&s_cs[jc + 2 * tg];
        const float2 csB = *(const float2*)&s_cs[jc + 8 + 2 * tg];
        float p[8];
        p[0] = ex2a(fminf(fmaf(m2g, S[0], base0 + csA.x), 0.0f));
        p[1] = ex2a(fminf(fmaf(m2g, S[1], base0 + csA.y), 0.0f));
        p[2] = ex2a(fminf(fmaf(m2g, S[2], base1 + csA.x), 0.0f));
        p[3] = ex2a(fminf(fmaf(m2g, S[3], base1 + csA.y), 0.0f));
        p[4] = ex2a(fminf(fmaf(m2g, S[4], base0 + csB.x), 0.0f));
        p[5] = ex2a(fminf(fmaf(m2g, S[5], base0 + csB.y), 0.0f));
        p[6] = ex2a(fminf(fmaf(m2g, S[6], base1 + csB.x), 0.0f));
        p[7] = ex2a(fminf(fmaf(m2g, S[7], base1 + csB.y), 0.0f));
        if (i0 == jglob) {   // uniform per warp-chunk; exact diagonal k = 1
            const int jA = jglob + 2 * tg, jB = jglob + 8 + 2 * tg;
            if (row0 == jA)     p[0] = 1.0f;
            if (row0 == jA + 1) p[1] = 1.0f;
            if (row1 == jA)     p[2] = 1.0f;
            if (row1 == jA + 1) p[3] = 1.0f;
            if (row0 == jB)     p[4] = 1.0f;
            if (row0 == jB + 1) p[5] = 1.0f;
            if (row1 == jB)     p[6] = 1.0f;
            if (row1 == jB + 1) p[7] = 1.0f;
        }
        // D-fragment pair -> A-fragment repack (register-exact), hi/lo split
        uint32_t Ph[4], Pl[4];
        hilo2(p[0], p[1], Ph[0], Pl[0]);
        hilo2(p[2], p[3], Ph[1], Pl[1]);
        hilo2(p[4], p[5], Ph[2], Pl[2]);
        hilo2(p[6], p[7], Ph[3], Pl[3]);
#pragma unroll
        for (int nh = 0; nh < 2; nh++) {
            const int dr = nh * 8 + g;
            uint32_t vh0 = *(const uint32_t*)&s_vth[dr * VROW + jc + 2 * tg];
            uint32_t vh1 = *(const uint32_t*)&s_vth[dr * VROW + jc + 2 * tg + 8];
            uint32_t vl0 = *(const uint32_t*)&s_vtl[dr * VROW + jc + 2 * tg];
            uint32_t vl1 = *(const uint32_t*)&s_vtl[dr * VROW + jc + 2 * tg + 8];
            mma16816(Wacc + nh * 4, Ph, vh0, vh1);
            mma16816(Wacc + nh * 4, Pl, vh0, vh1);
            mma16816(Wacc + nh * 4, Ph, vl0, vl1);
        }
    };

#pragma unroll 1
    for (int t = 0; t < TILES_PER_CTA; t++) {
        const int jt = blockIdx.y * (N / JS) + t * JT;
        __syncthreads();   // everyone done reading previous tile

        // ---- fill shared: Xj hi/lo [j][d], V^T hi/lo [d][j], cs ----
        {
            const int r  = tid >> 1;
            const int dh = (tid & 1) * 8;
            const float4* xr = (const float4*)(X + (size_t)(jt + r) * D + dh);
            float4 a = xr[0], b = xr[1];
            uint32_t h0, l0, h1, l1, h2, l2, h3, l3;
            hilo2(a.x, a.y, h0, l0);
            hilo2(a.z, a.w, h1, l1);
            hilo2(b.x, b.y, h2, l2);
            hilo2(b.z, b.w, h3, l3);
            *(uint4*)(s_xh + r * XROW + dh * 2) = make_uint4(h0, h1, h2, h3);
            *(uint4*)(s_xl + r * XROW + dh * 2) = make_uint4(l0, l1, l2, l3);

            const float4* vr = (const float4*)(V + (size_t)(jt + r) * D + dh);
            float4 va = vr[0], vb = vr[1];
            float vv[8] = {va.x, va.y, va.z, va.w, vb.x, vb.y, vb.z, vb.w};
#pragma unroll
            for (int d = 0; d < 8; d++) {
                __nv_bfloat16 hb = __float2bfloat16(vv[d]);
                s_vth[(dh + d) * VROW + r] = hb;
                s_vtl[(dh + d) * VROW + r] =
                    __float2bfloat16(vv[d] - __bfloat162float(hb));
            }
            if (tid < JT) s_cs[tid] = gamma * g_sq[jt + tid];
        }
        __syncthreads();

        // ---- 2-chunk software pipeline over the 8 chunks of this tile ----
        float Sa[8], Sb[8];
        mma1(0, Sa);
#pragma unroll 1
        for (int c = 0; c < CHUNKS_PER_TILE; c += 2) {
            const int jc0 = c * 16;
            mma1(jc0 + 16, Sb);                 // next chunk's MMA1, independent
            epi_mma2(jc0, jt + jc0, Sa);        // current chunk epilogue + MMA2
            if (c + 2 < CHUNKS_PER_TILE) mma1(jc0 + 32, Sa);
            epi_mma2(jc0 + 16, jt + jc0 + 16, Sb);
        }
    }

    // ---- writeback ----
#pragma unroll
    for (int nh = 0; nh < 2; nh++) {
        const int col = nh * 8 + 2 * tg;
        atomicAdd(&Wout[(size_t)row0 * D + col],     Wacc[nh * 4 + 0]);
        atomicAdd(&Wout[(size_t)row0 * D + col + 1], Wacc[nh * 4 + 1]);
        atomicAdd(&Wout[(size_t)row1 * D + col],     Wacc[nh * 4 + 2]);
        atomicAdd(&Wout[(size_t)row1 * D + col + 1], Wacc[nh * 4 + 3]);
    }
}

// ---------------------------------------------------------------------------
__global__ void __launch_bounds__(256) mid_kernel(const float* __restrict__ Y) {
    int k = blockIdx.x * 256 + threadIdx.x;
    g_diff[k] = g_A[k] - Y[k];
    g_W[k] = 0.0f;
}

__global__ void __launch_bounds__(256) final_kernel(const float* __restrict__ Lam,
                                                    float* __restrict__ out) {
    __shared__ float s_red[8];
    float s = 0.0f;
    for (int k = blockIdx.x * 256 + threadIdx.x; k < N * D; k += gridDim.x * 256)
        s += g_diff[k] * g_W[k] + 0.01f * Lam[k] * g_A[k];
#pragma unroll
    for (int o = 16; o > 0; o >>= 1) s += __shfl_xor_sync(0xffffffffu, s, o);
    const int lane = threadIdx.x & 31, wd = threadIdx.x >> 5;
    if (lane == 0) s_red[wd] = s;
    __syncthreads();
    if (threadIdx.x == 0) {
        float t = 0.0f;
#pragma unroll
        for (int q = 0; q < 8; q++) t += s_red[q];
        atomicAdd(out, t);
    }
}

// ---------------------------------------------------------------------------
extern "C" void kernel_launch(void* const* d_in, const int* in_sizes, int n_in,
                              void* d_out, int out_size) {
    const float* X   = (const float*)d_in[0];
    const float* Y   = (const float*)d_in[1];
    const float* Lam = (const float*)d_in[2];
    float* out = (float*)d_out;

    prep_kernel<<<N / 256, 256>>>(X, out);

    dim3 grid(N / 128, JS);
    rbf_mv_kernel<<<grid, 256>>>(X, Lam, GAMMA1, 0);   // A = Kfit @ Lam
    mid_kernel<<<N * D / 256, 256>>>(Y);               // diff = A - Y, W = 0
    rbf_mv_kernel<<<grid, 256>>>(X, Lam, GAMMA2, 1);   // W = Kmmd @ diff
    final_kernel<<<128, 256>>>(Lam, out);
}